// round 5
// baseline (speedup 1.0000x reference)
#include <cuda_runtime.h>
#include <math.h>

// ---------------------------------------------------------------------------
// PSA quaternion block on GB300. Layouts:
//   activations: [B=4, C, 4, HW=1024] (float), per-batch a row-major (C*4) x 1024 matrix
//   quaternion weights: [4, Cout, Cin, kh, kw]
// Hamilton product folded into real GEMM via (WIDX, SGN) tables.
// ---------------------------------------------------------------------------

__constant__ int   c_WIDX[16] = {0,1,2,3,  1,0,3,2,  2,3,0,1,  3,2,1,0};
__constant__ float c_SGN [16] = {1,-1,-1,-1,  1,1,1,-1,  1,-1,1,1,  1,1,-1,1};

// ------------------------------ scratch ------------------------------------
__device__ float g_h1 [4*512*1024];   // cv1 out / after bn1+relu   [4,128,4,1024]
__device__ float g_qkv[4*768*1024];   // qkv out                    [4,192,4,1024]
__device__ float g_o  [4*256*1024];   // attention out (reused as ffn2 raw out)
__device__ float g_o2 [4*256*1024];   // o + pe
__device__ float g_p  [4*256*1024];   // proj out / attn_norm in-place
__device__ float g_f1 [4*512*1024];   // ffn1 out (reused as cv2 raw out)
__device__ float g_cat[4*512*1024];   // concat buffer
__device__ float g_Wcv1 [512*512];
__device__ float g_Wqkv [768*256];
__device__ float g_Wproj[256*256];
__device__ float g_Wffn1[512*256];
__device__ float g_Wffn2[256*512];
__device__ float g_Wcv2 [512*512];

// ---------------------- expand quaternion weight ---------------------------
// w: [4, Cout, Cin] (1x1).  Weff: [(Cout*4) x (Cin*4)] row-major.
__global__ void expand_kernel(const float* __restrict__ w, float* __restrict__ Weff,
                              int Cout, int Cin)
{
    int idx = blockIdx.x * blockDim.x + threadIdx.x;
    int K4 = Cin * 4;
    int total = Cout * 4 * K4;
    if (idx >= total) return;
    int k = idx % K4;
    int m = idx / K4;
    int co = m & 3, oc = m >> 2;
    int ci = k & 3, ic = k >> 2;
    int wc  = c_WIDX[co*4 + ci];
    float s = c_SGN [co*4 + ci];
    Weff[idx] = s * w[((size_t)wc * Cout + oc) * Cin + ic];
}

// ------------------------------- GEMM --------------------------------------
// Y_b[M x 1024] = W[M x K] * X_b[K x 1024]  (+ bias[m]) for b in 0..3
// block: 128(m) x 64(n) tile, 256 threads, 8x4 per thread, BK=16.
__global__ __launch_bounds__(256) void qgemm_kernel(
    const float* __restrict__ W, const float* __restrict__ X,
    float* __restrict__ Y, const float* __restrict__ bias,
    int K, int in_bs, int out_bs)
{
    const int b  = blockIdx.z;
    const int m0 = blockIdx.y * 128;
    const int n0 = blockIdx.x * 64;
    const float* Xb = X + (size_t)b * in_bs;
    float* Yb = Y + (size_t)b * out_bs;

    __shared__ float As[16][128];
    __shared__ float Bs[16][64];

    const int tid = threadIdx.x;
    const int tx = tid & 15;   // n
    const int ty = tid >> 4;   // m

    float acc[8][4];
#pragma unroll
    for (int i = 0; i < 8; i++)
#pragma unroll
        for (int j = 0; j < 4; j++) acc[i][j] = 0.f;

    for (int k0 = 0; k0 < K; k0 += 16) {
        // A tile: 128 m x 16 k = 512 float4 loads (each thread 2)
#pragma unroll
        for (int i = 0; i < 2; i++) {
            int f = tid + i * 256;      // 0..511
            int m = f >> 2;             // 0..127
            int kq = (f & 3) * 4;       // 0,4,8,12
            float4 w4 = *(const float4*)&W[(size_t)(m0 + m) * K + k0 + kq];
            As[kq + 0][m] = w4.x;
            As[kq + 1][m] = w4.y;
            As[kq + 2][m] = w4.z;
            As[kq + 3][m] = w4.w;
        }
        // B tile: 16 k x 64 n = 256 float4 loads (each thread 1)
        {
            int k  = tid >> 4;
            int nq = (tid & 15) * 4;
            *(float4*)&Bs[k][nq] = *(const float4*)&Xb[(size_t)(k0 + k) * 1024 + n0 + nq];
        }
        __syncthreads();
#pragma unroll
        for (int kk = 0; kk < 16; kk++) {
            float a[8], bb[4];
            *(float4*)&a[0] = *(float4*)&As[kk][ty * 8];
            *(float4*)&a[4] = *(float4*)&As[kk][ty * 8 + 4];
            *(float4*)&bb[0] = *(float4*)&Bs[kk][tx * 4];
#pragma unroll
            for (int i = 0; i < 8; i++)
#pragma unroll
                for (int j = 0; j < 4; j++)
                    acc[i][j] += a[i] * bb[j];
        }
        __syncthreads();
    }
#pragma unroll
    for (int i = 0; i < 8; i++) {
        int m = m0 + ty * 8 + i;
        float bv = bias ? bias[m] : 0.f;
        float4 r = make_float4(acc[i][0] + bv, acc[i][1] + bv,
                               acc[i][2] + bv, acc[i][3] + bv);
        *(float4*)&Yb[(size_t)m * 1024 + n0 + tx * 4] = r;
    }
}

// ------------------------------- IQBN --------------------------------------
// one block per (channel,component) = c4; stats over B*HW = 4096 elems.
__global__ __launch_bounds__(256) void iqbn_kernel(
    const float* __restrict__ x, float* __restrict__ y,
    const float* __restrict__ gam, const float* __restrict__ bet,
    int in_bs, int out_bs, int do_relu)
{
    int c4 = blockIdx.x;
    int tid = threadIdx.x;
    float v[16];
    float s = 0.f, ss = 0.f;
#pragma unroll
    for (int i = 0; i < 16; i++) {
        int e = tid + (i << 8);
        int bb = e >> 10, hw = e & 1023;
        float t = x[(size_t)bb * in_bs + (size_t)c4 * 1024 + hw];
        v[i] = t; s += t; ss += t * t;
    }
    __shared__ float rs[256], rq[256];
    rs[tid] = s; rq[tid] = ss;
    __syncthreads();
    for (int o = 128; o > 0; o >>= 1) {
        if (tid < o) { rs[tid] += rs[tid + o]; rq[tid] += rq[tid + o]; }
        __syncthreads();
    }
    float mean = rs[0] * (1.0f / 4096.0f);
    float var  = rq[0] * (1.0f / 4096.0f) - mean * mean;
    float rstd = rsqrtf(var + 1e-5f);
    float gg = gam[c4] * rstd;
    float bb2 = bet[c4] - mean * gg;
#pragma unroll
    for (int i = 0; i < 16; i++) {
        int e = tid + (i << 8);
        int bb = e >> 10, hw = e & 1023;
        float t = v[i] * gg + bb2;
        if (do_relu) t = fmaxf(t, 0.f);
        y[(size_t)bb * out_bs + (size_t)c4 * 1024 + hw] = t;
    }
}

// ----------------------------- attention -----------------------------------
// grid (64, 2): blockIdx.x = (b*4+h)*4+qc, blockIdx.y = query half.
// 512 threads, one query per thread, online softmax, K/V in 128KB smem.
__global__ __launch_bounds__(512) void attn_kernel(const float* __restrict__ qkv,
                                                   float* __restrict__ o)
{
    extern __shared__ float sm[];
    float* Ks = sm;               // [16][1024]
    float* Vs = sm + 16 * 1024;   // [16][1024]
    int combo = blockIdx.x;
    int qc = combo & 3;
    int hh = (combo >> 2) & 3;
    int bb = combo >> 4;
    int tid = threadIdx.x;
    const size_t cs = 4 * 1024;   // channel stride
    const float* qb = qkv + (((size_t)bb * 192 + hh * 48 +  0) * 4 + qc) * 1024;
    const float* kb = qkv + (((size_t)bb * 192 + hh * 48 + 16) * 4 + qc) * 1024;
    const float* vb = qkv + (((size_t)bb * 192 + hh * 48 + 32) * 4 + qc) * 1024;

    for (int i = tid; i < 16 * 1024; i += 512) {
        int d = i >> 10, m = i & 1023;
        Ks[i] = kb[d * cs + m];
        Vs[i] = vb[d * cs + m];
    }
    __syncthreads();

    int n = blockIdx.y * 512 + tid;
    float q[16];
#pragma unroll
    for (int d = 0; d < 16; d++) q[d] = qb[d * cs + n] * 0.25f;  // fold scale

    float mmax = -1e30f, l = 0.f;
    float acc[16];
#pragma unroll
    for (int d = 0; d < 16; d++) acc[d] = 0.f;

    for (int mv = 0; mv < 256; mv++) {
        float4 s4 = make_float4(0.f, 0.f, 0.f, 0.f);
#pragma unroll
        for (int d = 0; d < 16; d++) {
            float4 kv = *(const float4*)&Ks[d * 1024 + mv * 4];
            float qd = q[d];
            s4.x += qd * kv.x; s4.y += qd * kv.y;
            s4.z += qd * kv.z; s4.w += qd * kv.w;
        }
        float tmax = fmaxf(fmaxf(s4.x, s4.y), fmaxf(s4.z, s4.w));
        float nm = fmaxf(mmax, tmax);
        float corr = __expf(mmax - nm);
        float p0 = __expf(s4.x - nm);
        float p1 = __expf(s4.y - nm);
        float p2 = __expf(s4.z - nm);
        float p3 = __expf(s4.w - nm);
        l = l * corr + (p0 + p1 + p2 + p3);
#pragma unroll
        for (int d = 0; d < 16; d++) {
            float4 vv = *(const float4*)&Vs[d * 1024 + mv * 4];
            acc[d] = acc[d] * corr + p0 * vv.x + p1 * vv.y + p2 * vv.z + p3 * vv.w;
        }
        mmax = nm;
    }
    float inv = 1.f / l;
#pragma unroll
    for (int d = 0; d < 16; d++)
        o[(((size_t)bb * 64 + hh * 16 + d) * 4 + qc) * 1024 + n] = acc[d] * inv;
}

// --------------------- 3x3 grouped quaternion PE conv ----------------------
// groups=16, Cin/g=Cout/g=4.  block = (b*64+oc)*4+co, thread = y*32+x.
// o2 = o + pe(o) + pe_b
__global__ __launch_bounds__(1024) void pe_kernel(
    const float* __restrict__ o, const float* __restrict__ pw,
    const float* __restrict__ pb, float* __restrict__ o2)
{
    int blk = blockIdx.x;
    int co = blk & 3;
    int oc = (blk >> 2) & 63;
    int bb = blk >> 8;
    int t = threadIdx.x;
    int y = t >> 5, xq = t & 31;
    int g = oc >> 2;

    float acc = pb[oc * 4 + co];
#pragma unroll
    for (int ci = 0; ci < 4; ci++) {
        int wc  = c_WIDX[co * 4 + ci];
        float s = c_SGN [co * 4 + ci];
#pragma unroll
        for (int ic = 0; ic < 4; ic++) {
            const float* xp = o  + (((size_t)bb * 64 + g * 4 + ic) * 4 + ci) * 1024;
            const float* wp = pw + (((size_t)wc * 64 + oc) * 4 + ic) * 9;
            float sum = 0.f;
#pragma unroll
            for (int ky = 0; ky < 3; ky++) {
                int yy = y + ky - 1;
                if (yy < 0 || yy > 31) continue;
#pragma unroll
                for (int kx = 0; kx < 3; kx++) {
                    int xx = xq + kx - 1;
                    if (xx < 0 || xx > 31) continue;
                    sum += xp[yy * 32 + xx] * wp[ky * 3 + kx];
                }
            }
            acc += s * sum;
        }
    }
    size_t oi = (((size_t)bb * 64 + oc) * 4 + co) * 1024 + t;
    o2[oi] = o[oi] + acc;
}

// ---------------------- copy b-branch into concat --------------------------
__global__ void copy_b_kernel(const float* __restrict__ h1, float* __restrict__ cat)
{
    int i = blockIdx.x * blockDim.x + threadIdx.x;  // < 1048576
    int hw = i & 1023;
    int c4 = (i >> 10) & 255;
    int bb = i >> 18;
    size_t off = ((size_t)bb * 512 + 256 + c4) * 1024 + hw;
    cat[off] = h1[off];
}

// ---------------------------------------------------------------------------
extern "C" void kernel_launch(void* const* d_in, const int* in_sizes, int n_in,
                              void* d_out, int out_size)
{
    const float* x          = (const float*)d_in[0];
    const float* cv1_w      = (const float*)d_in[1];
    const float* bn1_g      = (const float*)d_in[2];
    const float* bn1_b      = (const float*)d_in[3];
    const float* qkv_w      = (const float*)d_in[4];
    const float* qkv_b      = (const float*)d_in[5];
    const float* proj_w     = (const float*)d_in[6];
    const float* proj_b     = (const float*)d_in[7];
    const float* pe_w       = (const float*)d_in[8];
    const float* pe_b       = (const float*)d_in[9];
    const float* an_g       = (const float*)d_in[10];
    const float* an_b       = (const float*)d_in[11];
    const float* ffn1_w     = (const float*)d_in[12];
    const float* fbn1_g     = (const float*)d_in[13];
    const float* fbn1_b     = (const float*)d_in[14];
    const float* ffn2_w     = (const float*)d_in[15];
    const float* fbn2_g     = (const float*)d_in[16];
    const float* fbn2_b     = (const float*)d_in[17];
    const float* cv2_w      = (const float*)d_in[18];
    const float* bn2_g      = (const float*)d_in[19];
    const float* bn2_b      = (const float*)d_in[20];
    float* out = (float*)d_out;

    float *h1, *qkv, *o, *o2, *p, *f1, *cat;
    float *W1, *W2, *W3, *W4, *W5, *W6;
    cudaGetSymbolAddress((void**)&h1,  g_h1);
    cudaGetSymbolAddress((void**)&qkv, g_qkv);
    cudaGetSymbolAddress((void**)&o,   g_o);
    cudaGetSymbolAddress((void**)&o2,  g_o2);
    cudaGetSymbolAddress((void**)&p,   g_p);
    cudaGetSymbolAddress((void**)&f1,  g_f1);
    cudaGetSymbolAddress((void**)&cat, g_cat);
    cudaGetSymbolAddress((void**)&W1,  g_Wcv1);
    cudaGetSymbolAddress((void**)&W2,  g_Wqkv);
    cudaGetSymbolAddress((void**)&W3,  g_Wproj);
    cudaGetSymbolAddress((void**)&W4,  g_Wffn1);
    cudaGetSymbolAddress((void**)&W5,  g_Wffn2);
    cudaGetSymbolAddress((void**)&W6,  g_Wcv2);

    cudaFuncSetAttribute(attn_kernel, cudaFuncAttributeMaxDynamicSharedMemorySize,
                         131072);

    const int BS512 = 512 * 1024;   // batch stride for 128-channel tensors
    const int BS768 = 768 * 1024;
    const int BS256 = 256 * 1024;

    // 1) cv1 + bn1 + relu  -> h1
    expand_kernel<<<(512 * 512 + 255) / 256, 256>>>(cv1_w, W1, 128, 128);
    qgemm_kernel<<<dim3(16, 4, 4), 256>>>(W1, x, h1, nullptr, 512, BS512, BS512);
    iqbn_kernel<<<512, 256>>>(h1, h1, bn1_g, bn1_b, BS512, BS512, 1);

    // 2) qkv = qconv(a) + bias  (a = h1 channels 0..63)
    expand_kernel<<<(768 * 256 + 255) / 256, 256>>>(qkv_w, W2, 192, 64);
    qgemm_kernel<<<dim3(16, 6, 4), 256>>>(W2, h1, qkv, qkv_b, 256, BS512, BS768);

    // 3) attention -> o
    attn_kernel<<<dim3(64, 2), 512, 131072>>>(qkv, o);

    // 4) o2 = o + pe(o) + pe_b
    pe_kernel<<<1024, 1024>>>(o, pe_w, pe_b, o2);

    // 5) proj + bias -> p, then attn_norm (no relu) in place
    expand_kernel<<<(256 * 256 + 255) / 256, 256>>>(proj_w, W3, 64, 64);
    qgemm_kernel<<<dim3(16, 2, 4), 256>>>(W3, o2, p, proj_b, 256, BS256, BS256);
    iqbn_kernel<<<256, 256>>>(p, p, an_g, an_b, BS256, BS256, 0);

    // 6) ffn1 + bn + relu -> f1
    expand_kernel<<<(512 * 256 + 255) / 256, 256>>>(ffn1_w, W4, 128, 64);
    qgemm_kernel<<<dim3(16, 4, 4), 256>>>(W4, p, f1, nullptr, 256, BS256, BS512);
    iqbn_kernel<<<512, 256>>>(f1, f1, fbn1_g, fbn1_b, BS512, BS512, 1);

    // 7) ffn2 -> (reuse o), bn -> cat channels 0..63
    expand_kernel<<<(256 * 512 + 255) / 256, 256>>>(ffn2_w, W5, 64, 128);
    qgemm_kernel<<<dim3(16, 2, 4), 256>>>(W5, f1, o, nullptr, 512, BS512, BS256);
    iqbn_kernel<<<256, 256>>>(o, cat, fbn2_g, fbn2_b, BS256, BS512, 0);

    // 8) concat: cat channels 64..127 = h1 channels 64..127
    copy_b_kernel<<<4096, 256>>>(h1, cat);

    // 9) cv2 -> (reuse f1), bn2 + relu -> d_out
    expand_kernel<<<(512 * 512 + 255) / 256, 256>>>(cv2_w, W6, 128, 128);
    qgemm_kernel<<<dim3(16, 4, 4), 256>>>(W6, cat, f1, nullptr, 512, BS512, BS512);
    iqbn_kernel<<<512, 256>>>(f1, out, bn2_g, bn2_b, BS512, BS512, 1);
}